// round 11
// baseline (speedup 1.0000x reference)
#include <cuda_runtime.h>
#include <math_constants.h>

// ROI max pooling, smem-staged, float4 lanes.
// fm: (16 imgs, 16, 16, 512) f32; rois: (1024,4); out: (1024, 7, 7, 512) f32
//
// Grid (16 slices, 16 imgs, 2 roi-halves) = 512 blocks x 256 threads.
// Block stages a 32-channel image slice (256 px * 128B = 32KB) into smem.
// Warp = 4 ROIs x 8 float4-groups (lane>>3 = roi, lane&7 = group).
// Interior bins: single LDS.128 + STG.128 per 4-ROI bin.

#define FM_H 16
#define FM_W 16
#define PH 7
#define PW 7
#define C4T 128          // 512 ch / 4 (source/output row in float4)
#define SLICE_C4 8       // 32 ch per slice, in float4
#define NPIX 256
#define BIN_STRIDE4 128  // float4 stride between bins in output

__device__ __forceinline__ float4 f4max(float4 a, float4 b) {
    a.x = fmaxf(a.x, b.x);
    a.y = fmaxf(a.y, b.y);
    a.z = fmaxf(a.z, b.z);
    a.w = fmaxf(a.w, b.w);
    return a;
}

__global__ __launch_bounds__(256, 4) void roipool_kernel(
    const float4* __restrict__ fm,     // (16, 256, 128) float4
    const float4* __restrict__ rois,   // (1024) float4
    float4*       __restrict__ out)    // (1024, 49, 128) float4
{
    __shared__ float4 tile4[NPIX * SLICE_C4];   // 32 KB
    const int slice = blockIdx.x;   // 0..15
    const int img   = blockIdx.y;   // 0..15
    const int half  = blockIdx.z;   // 0..1
    const int tid   = threadIdx.x;  // 0..255

    // ---- Stage the 32-channel slice: 2048 float4, coalesced ----
    {
        const float4* src = fm + (size_t)img * (NPIX * C4T) + slice * SLICE_C4;
        #pragma unroll
        for (int i = 0; i < 8; ++i) {
            int idx = i * 256 + tid;
            tile4[idx] = __ldg(src + (idx >> 3) * C4T + (idx & 7));
        }
    }
    __syncthreads();

    const int warp = tid >> 5;          // 0..7
    const int lane = tid & 31;
    const int roi4 = lane >> 3;         // 0..3  (ROI within warp)
    const int grp  = lane & 7;          // 0..7  (float4 group in slice)
    const int g    = img * 64 + half * 32 + warp * 4 + roi4;

    const float4 r = __ldg(&rois[g]);
    // Truncation matches jnp .astype(int32) for positive values.
    const int h0 = (int)(16.0f * r.x);
    const int w0 = (int)(16.0f * r.y);
    const int h1 = (int)(16.0f * r.z);
    const int w1 = (int)(16.0f * r.w);
    const int hs = (h1 - h0) / PH;
    const int ws = (w1 - w0) / PW;

    // 32-bit float4 offsets (max ~6.4M; fits int)
    const float4* t     = tile4 + grp;
    float4*       obase = out + g * (PH * PW * C4T) + slice * SLICE_C4 + grp;

    if (hs == 1 && ws == 1) {
        const int nrl = h1 - h0 - (PH - 1);   // >= 1
        const int ncl = w1 - w0 - (PW - 1);   // >= 1
        const float4* p00 = t + (h0 * FM_W + w0) * SLICE_C4;

        // 36 interior 1x1 bins: bare LDS.128 -> STG.128, immediate offsets.
        #pragma unroll
        for (int bi = 0; bi < PH - 1; ++bi)
            #pragma unroll
            for (int bj = 0; bj < PW - 1; ++bj)
                obase[(bi * PW + bj) * BIN_STRIDE4] =
                    p00[(bi * FM_W + bj) * SLICE_C4];

        // Right column (bj=6): 1 x ncl.
        #pragma unroll
        for (int bi = 0; bi < PH - 1; ++bi) {
            const float4* p = p00 + (bi * FM_W + (PW - 1)) * SLICE_C4;
            float4 m = p[0];
            for (int c = 1; c < ncl; ++c) m = f4max(m, p[c * SLICE_C4]);
            obase[(bi * PW + (PW - 1)) * BIN_STRIDE4] = m;
        }
        // Bottom row (bi=6): nrl x 1.
        #pragma unroll
        for (int bj = 0; bj < PW - 1; ++bj) {
            const float4* p = p00 + ((PH - 1) * FM_W + bj) * SLICE_C4;
            float4 m = p[0];
            for (int rr = 1; rr < nrl; ++rr)
                m = f4max(m, p[rr * (FM_W * SLICE_C4)]);
            obase[((PH - 1) * PW + bj) * BIN_STRIDE4] = m;
        }
        // Corner: nrl x ncl.
        {
            const float4* p = p00 + ((PH - 1) * FM_W + (PW - 1)) * SLICE_C4;
            float4 m = p[0];
            for (int rr = 0; rr < nrl; ++rr)
                for (int c = 0; c < ncl; ++c)
                    if (rr | c) m = f4max(m, p[(rr * FM_W + c) * SLICE_C4]);
            obase[(PH * PW - 1) * BIN_STRIDE4] = m;
        }
    } else {
        // General path (reference semantics incl. empty bins -> -inf).
        #pragma unroll
        for (int bi = 0; bi < PH; ++bi) {
            int rs_, nr_;
            if (hs > 0) { rs_ = h0 + bi * hs; nr_ = (bi == PH - 1) ? (h1 - rs_) : hs; }
            else        { rs_ = h0;           nr_ = (bi == PH - 1) ? (h1 - h0) : 0; }
            #pragma unroll
            for (int bj = 0; bj < PW; ++bj) {
                int cs_, nc_;
                if (ws > 0) { cs_ = w0 + bj * ws; nc_ = (bj == PW - 1) ? (w1 - cs_) : ws; }
                else        { cs_ = w0;           nc_ = (bj == PW - 1) ? (w1 - w0) : 0; }
                float4 m = make_float4(-CUDART_INF_F, -CUDART_INF_F,
                                       -CUDART_INF_F, -CUDART_INF_F);
                const float4* p = t + (rs_ * FM_W + cs_) * SLICE_C4;
                for (int rr = 0; rr < nr_; ++rr)
                    for (int c = 0; c < nc_; ++c)
                        m = f4max(m, p[(rr * FM_W + c) * SLICE_C4]);
                obase[(bi * PW + bj) * BIN_STRIDE4] = m;
            }
        }
    }
}

extern "C" void kernel_launch(void* const* d_in, const int* in_sizes, int n_in,
                              void* d_out, int out_size) {
    const float4* fm   = (const float4*)d_in[0];
    const float4* rois = (const float4*)d_in[1];
    float4*       out  = (float4*)d_out;

    dim3 grid(16, 16, 2);   // slices x images x roi-halves
    roipool_kernel<<<grid, 256>>>(fm, rois, out);
}